// round 11
// baseline (speedup 1.0000x reference)
#include <cuda_runtime.h>
#include <math.h>

#define SR_F        24000.0f
#define INV_SR_F    (1.0f / 24000.0f)
#define TWO_PI_F    6.2831855f          /* fl32(2*pi) */
#define PI_F        3.1415927f          /* fl32(pi) */
#define HALF_STATIC 1200                /* ceil(5 * 0.01 * 24000) */
#define THREADS     128
#define ATOMS_PER_BLOCK 4               /* one warp per atom */
#define MAX_SAMPLES 240000
#define HALF_LOG2E  0.7213475204444817f /* 0.5 * log2(e) */

// Precomputed t[idx] = div.full.f32(idx, 24000) — bit-identical to the
// reference's t (XLA:GPU lowers f32 divide to div.full). Refilled every call.
__device__ __align__(16) float g_t_table[MAX_SAMPLES];

__device__ __forceinline__ float div_full(float a, float b) {
    float r;
    asm("div.full.f32 %0, %1, %2;" : "=f"(r) : "f"(a), "f"(b));
    return r;
}
__device__ __forceinline__ float ex2_approx(float x) {
    float r;
    asm("ex2.approx.f32 %0, %1;" : "=f"(r) : "f"(x));
    return r;
}
__device__ __forceinline__ float cos_approx(float x) {
    float r;
    asm("cos.approx.f32 %0, %1;" : "=f"(r) : "f"(x));
    return r;
}

// Init: zero output + fill t-table, vectorized (240000 % 4 == 0).
__global__ void gabor_init_kernel(float4* __restrict__ out4, int n4) {
    int i = blockIdx.x * blockDim.x + threadIdx.x;
    if (i < n4) {
        out4[i] = make_float4(0.f, 0.f, 0.f, 0.f);
        int b = i * 4;
        float4 tv;
        tv.x = div_full((float)(b    ), SR_F);
        tv.y = div_full((float)(b + 1), SR_F);
        tv.z = div_full((float)(b + 2), SR_F);
        tv.w = div_full((float)(b + 3), SR_F);
        reinterpret_cast<float4*>(g_t_table)[i] = tv;
    }
}

// Per-lane evaluation, amplitude folded into the transcendentals:
//   env' = ex2(envc*dt^2 + log2|a|),  val = env' * cos(om_w*dt + g_w*dt^2 + ph')
__device__ __forceinline__ float gabor_eval(float t, float tu, float envc,
                                            float l2a, float om_w, float g_w,
                                            float ph) {
    const float dt    = __fadd_rn(t, -tu);          // bit-exact dt
    const float dt2   = __fmul_rn(dt, dt);
    const float env   = ex2_approx(fmaf(envc, dt2, l2a));
    const float phase = fmaf(om_w, dt, fmaf(g_w, dt2, ph));
    return __fmul_rn(env, cos_approx(phase));
}

__device__ __forceinline__ void eval4_red(const float4 tv, int i0,
                                          float tu, float envc, float l2a,
                                          float om_w, float g_w, float ph,
                                          float* __restrict__ out) {
    float4 val;
    val.x = gabor_eval(tv.x, tu, envc, l2a, om_w, g_w, ph);
    val.y = gabor_eval(tv.y, tu, envc, l2a, om_w, g_w, ph);
    val.z = gabor_eval(tv.z, tu, envc, l2a, om_w, g_w, ph);
    val.w = gabor_eval(tv.w, tu, envc, l2a, om_w, g_w, ph);
    atomicAdd(reinterpret_cast<float4*>(out + i0), val);     // RED.128
}

// One WARP per atom. Conservative (+/-2 padded) window; no per-sample mask
// (edge samples carry env <= e^-12.5 — a ~1e-7 rel effect). Each iteration
// issues TWO independent coalesced 512B table segments up front (MLP=2) to
// hide the ~240-cycle L2 latency of the t-table loads.
__global__
void gabor_render_kernel(const float* __restrict__ amplitude,
                         const float* __restrict__ tau,
                         const float* __restrict__ omega,
                         const float* __restrict__ sigma,
                         const float* __restrict__ phi,
                         const float* __restrict__ gamma,
                         float* __restrict__ out,
                         int num_samples) {
    const int wid  = (int)threadIdx.x >> 5;
    const int lane = (int)threadIdx.x & 31;
    const int atom = blockIdx.x * ATOMS_PER_BLOCK + wid;

    const float a  = __ldg(amplitude + atom);
    const float tu = __ldg(tau + atom);
    const float om = __ldg(omega + atom);
    const float sg = __ldg(sigma + atom);
    const float ph = __ldg(phi + atom);
    const float gm = __ldg(gamma + atom);

    const int   c    = __float2int_rn(__fmul_rn(tu, SR_F));  // jnp.round match
    const float r    = __fmul_rn(5.0f, sg);
    const float om_w = __fmul_rn(TWO_PI_F, om);              // rad/s
    const float g_w  = __fmul_rn(PI_F, gm);                  // rad/s^2
    const float inv_sg = __frcp_rn(sg);
    const float envc   = -__fmul_rn(HALF_LOG2E, __fmul_rn(inv_sg, inv_sg));
    const float l2a    = __log2f(fabsf(a));                  // fold |a| into ex2
    const float ph2    = (a < 0.0f) ? __fadd_rn(ph, PI_F) : ph;

    const float delta0 = fmaf((float)c, INV_SR_F, -tu);
    int jlo = (int)ceilf ((-r - delta0) * SR_F) - 2;
    int jhi = (int)floorf(( r - delta0) * SR_F) + 2;
    jlo = max(jlo, max(-HALF_STATIC, -c));
    jhi = min(jhi, min( HALF_STATIC, num_samples - 1 - c));
    if (jlo > jhi) return;

    const int lo4 = (c + jlo) & ~3;     // 4-aligned start (>= 0)
    const int hi4 = (c + jhi) & ~3;     // last vector start (hi4+3 <= 239999)

    const float* __restrict__ tp = g_t_table;

    // Warp covers 256 samples per iteration as two coalesced 512B segments.
    for (int i0 = lo4 + 4 * lane; i0 <= hi4; i0 += 256) {
        const int  i1   = i0 + 128;
        const bool has2 = (i1 <= hi4);
        // Issue both loads before any dependent math (MLP = 2).
        const float4 tv0 = __ldg(reinterpret_cast<const float4*>(tp + i0));
        float4 tv1 = make_float4(0.f, 0.f, 0.f, 0.f);
        if (has2) tv1 = __ldg(reinterpret_cast<const float4*>(tp + i1));

        eval4_red(tv0, i0, tu, envc, l2a, om_w, g_w, ph2, out);
        if (has2) eval4_red(tv1, i1, tu, envc, l2a, om_w, g_w, ph2, out);
    }
}

extern "C" void kernel_launch(void* const* d_in, const int* in_sizes, int n_in,
                              void* d_out, int out_size) {
    const float* amplitude = (const float*)d_in[0];
    const float* tau       = (const float*)d_in[1];
    const float* omega     = (const float*)d_in[2];
    const float* sigma     = (const float*)d_in[3];
    const float* phi       = (const float*)d_in[4];
    const float* gamma     = (const float*)d_in[5];
    float* out = (float*)d_out;

    const int num_atoms   = in_sizes[0];     // 16384
    const int num_samples = out_size;        // 240000

    {
        int n4 = num_samples / 4;
        int threads = 256;
        int blocks  = (n4 + threads - 1) / threads;
        gabor_init_kernel<<<blocks, threads>>>((float4*)out, n4);
    }
    gabor_render_kernel<<<num_atoms / ATOMS_PER_BLOCK, THREADS>>>(
        amplitude, tau, omega, sigma, phi, gamma, out, num_samples);
}